// round 1
// baseline (speedup 1.0000x reference)
#include <cuda_runtime.h>

#define H 4
#define Dh 64
#define HID 256
#define NGT 100000
#define NUBS 20000
#define NAG 20000
#define ESEEN 320000
#define ENEAR 160000

// ---------------- scratch (device globals, no runtime alloc) ----------------
// g_feat layout: fs_seen | fs_near | fd_seen | res_seen | fd_near | res_near
__device__ float g_feat[(NGT + NUBS + 4 * NAG) * HID];
__device__ float g_xcat[NAG * 2 * HID];
__device__ float g_sc[(ESEEN + ENEAR) * H];
__device__ int   g_cnt[2 * NAG];
__device__ int   g_cur[2 * NAG];
__device__ int   g_off[2 * (NAG + 1)];
__device__ int   g_perm[ESEEN + ENEAR];

#define FS_SEEN 0L
#define FS_NEAR ((long)NGT * HID)
#define FD_S    ((long)(NGT + NUBS) * HID)
#define RES_S   (FD_S + (long)NAG * HID)
#define FD_N    (RES_S + (long)NAG * HID)
#define RES_N   (FD_N + (long)NAG * HID)

// ---------------- zero counters ----------------
__global__ void k_zero() {
    int i = blockIdx.x * blockDim.x + threadIdx.x;
    if (i < 2 * NAG) g_cnt[i] = 0;
}

// ---------------- projection: out[n,256] = x[n,F] @ W[F,256] + b ----------------
template<int F>
__global__ void k_proj(const float* __restrict__ x, const float* __restrict__ W,
                       const float* __restrict__ b, int n, long out_off) {
    __shared__ float sW[F * HID];
    __shared__ float sb[HID];
    for (int i = threadIdx.x; i < F * HID; i += blockDim.x) sW[i] = W[i];
    for (int i = threadIdx.x; i < HID; i += blockDim.x) sb[i] = b[i];
    __syncthreads();
    int warp = threadIdx.x >> 5, lane = threadIdx.x & 31;
    int node = blockIdx.x * 8 + warp;
    if (node >= n) return;
    float xr[F];
#pragma unroll
    for (int k = 0; k < F; k++) xr[k] = __ldg(&x[(long)node * F + k]);
    float* out = g_feat + out_off + (long)node * HID;
#pragma unroll
    for (int c0 = 0; c0 < HID; c0 += 32) {
        int c = c0 + lane;
        float acc = sb[c];
#pragma unroll
        for (int k = 0; k < F; k++) acc = fmaf(xr[k], sW[k * HID + c], acc);
        out[c] = acc;
    }
}

// ---------------- CSR build ----------------
__global__ void k_hist(const int* __restrict__ dst, int e, int cnt_off) {
    for (int i = blockIdx.x * blockDim.x + threadIdx.x; i < e;
         i += gridDim.x * blockDim.x)
        atomicAdd(&g_cnt[cnt_off + dst[i]], 1);
}

__global__ void k_scan(int n) {
    int g = blockIdx.x;                      // graph 0 (seen) / 1 (near)
    const int* cnt = g_cnt + g * NAG;
    int* off = g_off + g * (NAG + 1);
    int* cur = g_cur + g * NAG;
    __shared__ int s[512];
    int t = threadIdx.x;
    int per = (n + 511) / 512;
    int lo = t * per;
    int hi = lo + per; if (hi > n) hi = n;
    int sum = 0;
    for (int i = lo; i < hi; i++) sum += cnt[i];
    s[t] = sum;
    __syncthreads();
    for (int d = 1; d < 512; d <<= 1) {
        int v = (t >= d) ? s[t - d] : 0;
        __syncthreads();
        s[t] += v;
        __syncthreads();
    }
    int pre = (t == 0) ? 0 : s[t - 1];
    for (int i = lo; i < hi; i++) {
        off[i] = pre;
        cur[i] = pre;
        pre += cnt[i];
    }
    if (t == 0) off[n] = s[511];
}

__global__ void k_scatter(const int* __restrict__ dst, int e, int g, int perm_base) {
    for (int i = blockIdx.x * blockDim.x + threadIdx.x; i < e;
         i += gridDim.x * blockDim.x) {
        int p = atomicAdd(&g_cur[g * NAG + dst[i]], 1);
        g_perm[perm_base + p] = i;
    }
}

// ---------------- GATv2 per (dst, head) warp ----------------
__global__ void k_gat(const float* __restrict__ attn, const int* __restrict__ src,
                      long fs_off, long fd_off, long res_off,
                      int off_base, int perm_base, int sc_base,
                      int xoff, int nag) {
    int warp = threadIdx.x >> 5, lane = threadIdx.x & 31;
    int dstn = blockIdx.x * 2 + (warp >> 2);
    if (dstn >= nag) return;
    int h = warp & 3;
    int base = h * Dh + lane * 2;
    float2 a   = *(const float2*)(attn + base);
    float2 fdv = *(const float2*)(g_feat + fd_off + (long)dstn * HID + base);
    float2 rv  = *(const float2*)(g_feat + res_off + (long)dstn * HID + base);
    int e0 = g_off[off_base + dstn], e1 = g_off[off_base + dstn + 1];

    // pass 1: scores + max
    float mx = -3.0e38f;
    for (int i = e0; i < e1; i++) {
        int s = src[g_perm[perm_base + i]];
        float2 f = *(const float2*)(g_feat + fs_off + (long)s * HID + base);
        float v0 = f.x + fdv.x; v0 = (v0 >= 0.f) ? v0 : 0.2f * v0;
        float v1 = f.y + fdv.y; v1 = (v1 >= 0.f) ? v1 : 0.2f * v1;
        float p = v0 * a.x + v1 * a.y;
#pragma unroll
        for (int o = 16; o; o >>= 1) p += __shfl_xor_sync(0xffffffffu, p, o);
        if (lane == 0) g_sc[(long)(sc_base + i) * H + h] = p;
        mx = fmaxf(mx, p);
    }
    __threadfence_block();
    __syncwarp();

    // pass 2: exp-weighted aggregation
    float den = 0.f, acc0 = 0.f, acc1 = 0.f;
    for (int i = e0; i < e1; i++) {
        float p = g_sc[(long)(sc_base + i) * H + h];
        float ex = __expf(p - mx);
        den += ex;
        int s = src[g_perm[perm_base + i]];
        float2 f = *(const float2*)(g_feat + fs_off + (long)s * HID + base);
        acc0 = fmaf(ex, f.x, acc0);
        acc1 = fmaf(ex, f.y, acc1);
    }
    if (e1 == e0) den = 1.f;    // zero-in-degree: rst = 0
    float o0 = fmaxf(acc0 / den + rv.x, 0.f);
    float o1 = fmaxf(acc1 / den + rv.y, 0.f);
    *(float2*)(g_xcat + (long)dstn * (2 * HID) + xoff + base) = make_float2(o0, o1);
}

// ---------------- final GEMM: out = relu(xcat[M,512] @ W[512,256] + b) ----------------
__global__ void k_gemm(const float* __restrict__ B, const float* __restrict__ bias,
                       float* __restrict__ C, int M) {
    const int K = 2 * HID, N = HID;
    __shared__ float sA[32][65];   // [k][m], padded
    __shared__ float sB[32][64];   // [k][n]
    int bm = blockIdx.y * 64, bn = blockIdx.x * 64;
    int tx = threadIdx.x & 15, ty = threadIdx.x >> 4;
    float acc[4][4] = {};
    for (int k0 = 0; k0 < K; k0 += 32) {
        for (int i = threadIdx.x; i < 64 * 32; i += 256) {
            int m = i >> 5, k = i & 31;
            int gm = bm + m;
            sA[k][m] = (gm < M) ? g_xcat[(long)gm * K + k0 + k] : 0.f;
        }
        for (int i = threadIdx.x; i < 32 * 64; i += 256) {
            int k = i >> 6, n = i & 63;
            sB[k][n] = B[(long)(k0 + k) * N + bn + n];
        }
        __syncthreads();
#pragma unroll
        for (int k = 0; k < 32; k++) {
            float ar[4], br[4];
#pragma unroll
            for (int i = 0; i < 4; i++) ar[i] = sA[k][ty * 4 + i];
#pragma unroll
            for (int j = 0; j < 4; j++) br[j] = sB[k][tx * 4 + j];
#pragma unroll
            for (int i = 0; i < 4; i++)
#pragma unroll
                for (int j = 0; j < 4; j++)
                    acc[i][j] = fmaf(ar[i], br[j], acc[i][j]);
        }
        __syncthreads();
    }
#pragma unroll
    for (int i = 0; i < 4; i++) {
        int m = bm + ty * 4 + i;
        if (m >= M) continue;
#pragma unroll
        for (int j = 0; j < 4; j++) {
            int n = bn + tx * 4 + j;
            C[(long)m * N + n] = fmaxf(acc[i][j] + bias[n], 0.f);
        }
    }
}

// ---------------- launch ----------------
extern "C" void kernel_launch(void* const* d_in, const int* in_sizes, int n_in,
                              void* d_out, int out_size) {
    const float* x_gt   = (const float*)d_in[0];
    const float* x_ubs  = (const float*)d_in[1];
    const float* x_ag   = (const float*)d_in[2];
    const int* seen_src = (const int*)d_in[3];
    const int* seen_dst = (const int*)d_in[4];
    const int* near_src = (const int*)d_in[5];
    const int* near_dst = (const int*)d_in[6];
    const float* Ws_seen = (const float*)d_in[7];
    const float* bs_seen = (const float*)d_in[8];
    const float* Wd_seen = (const float*)d_in[9];
    const float* bd_seen = (const float*)d_in[10];
    const float* attn_seen = (const float*)d_in[11];
    const float* Wr_seen = (const float*)d_in[12];
    const float* br_seen = (const float*)d_in[13];
    const float* Ws_near = (const float*)d_in[14];
    const float* bs_near = (const float*)d_in[15];
    const float* Wd_near = (const float*)d_in[16];
    const float* bd_near = (const float*)d_in[17];
    const float* attn_near = (const float*)d_in[18];
    const float* Wr_near = (const float*)d_in[19];
    const float* br_near = (const float*)d_in[20];
    const float* W_aggr  = (const float*)d_in[21];
    const float* b_aggr  = (const float*)d_in[22];
    float* out = (float*)d_out;

    int n_gt  = in_sizes[0] / 8;
    int n_ubs = in_sizes[1] / 8;
    int n_ag  = in_sizes[2] / 16;
    int e_seen = in_sizes[3];
    int e_near = in_sizes[5];

    k_zero<<<(2 * NAG + 255) / 256, 256>>>();

    k_proj<8><<<(n_gt + 7) / 8, 256>>>(x_gt, Ws_seen, bs_seen, n_gt, FS_SEEN);
    k_proj<8><<<(n_ubs + 7) / 8, 256>>>(x_ubs, Ws_near, bs_near, n_ubs, FS_NEAR);
    k_proj<16><<<(n_ag + 7) / 8, 256>>>(x_ag, Wd_seen, bd_seen, n_ag, FD_S);
    k_proj<16><<<(n_ag + 7) / 8, 256>>>(x_ag, Wr_seen, br_seen, n_ag, RES_S);
    k_proj<16><<<(n_ag + 7) / 8, 256>>>(x_ag, Wd_near, bd_near, n_ag, FD_N);
    k_proj<16><<<(n_ag + 7) / 8, 256>>>(x_ag, Wr_near, br_near, n_ag, RES_N);

    k_hist<<<256, 256>>>(seen_dst, e_seen, 0);
    k_hist<<<256, 256>>>(near_dst, e_near, NAG);
    k_scan<<<2, 512>>>(n_ag);
    k_scatter<<<256, 256>>>(seen_dst, e_seen, 0, 0);
    k_scatter<<<256, 256>>>(near_dst, e_near, 1, ESEEN);

    k_gat<<<(n_ag + 1) / 2, 256>>>(attn_seen, seen_src, FS_SEEN, FD_S, RES_S,
                                   0, 0, 0, 0, n_ag);
    k_gat<<<(n_ag + 1) / 2, 256>>>(attn_near, near_src, FS_NEAR, FD_N, RES_N,
                                   NAG + 1, ESEEN, ESEEN, HID, n_ag);

    k_gemm<<<dim3(HID / 64, (n_ag + 63) / 64), 256>>>(W_aggr, b_aggr, out, n_ag);
}

// round 2
// speedup vs baseline: 1.2133x; 1.2133x over previous
#include <cuda_runtime.h>

#define H 4
#define Dh 64
#define HID 256
#define NGT 100000
#define NUBS 20000
#define NAG 20000
#define ESEEN 320000
#define ENEAR 160000

// ---------------- scratch (device globals, no runtime alloc) ----------------
// g_feat layout: fs_seen | fs_near | fd_seen | res_seen | fd_near | res_near
__device__ float g_feat[(NGT + NUBS + 4 * NAG) * HID];
__device__ float g_xcat[NAG * 2 * HID];
__device__ int   g_cnt[2 * NAG];
__device__ int   g_cur[2 * NAG];
__device__ int   g_off[2 * (NAG + 1)];
__device__ int   g_perm[ESEEN + ENEAR];   // holds SRC node ids in dst-grouped order

#define FS_SEEN 0L
#define FS_NEAR ((long)NGT * HID)
#define FD_S    ((long)(NGT + NUBS) * HID)
#define RES_S   (FD_S + (long)NAG * HID)
#define FD_N    (RES_S + (long)NAG * HID)
#define RES_N   (FD_N + (long)NAG * HID)

// ---------------- zero counters ----------------
__global__ void k_zero() {
    int i = blockIdx.x * blockDim.x + threadIdx.x;
    if (i < 2 * NAG) g_cnt[i] = 0;
}

// ---------------- projection: out[n,256] = x[n,F] @ W[F,256] + b ----------------
// 64 nodes per block (8 per warp) so the W smem preload amortizes.
template<int F>
__device__ __forceinline__ void proj_body(const float* __restrict__ x,
                                          const float* __restrict__ W,
                                          const float* __restrict__ b,
                                          int n, long out_off) {
    __shared__ float sW[16 * HID];
    __shared__ float sb[HID];
    for (int i = threadIdx.x; i < F * HID; i += blockDim.x) sW[i] = W[i];
    for (int i = threadIdx.x; i < HID; i += blockDim.x) sb[i] = b[i];
    __syncthreads();
    int warp = threadIdx.x >> 5, lane = threadIdx.x & 31;
    int node0 = blockIdx.x * 64 + warp * 8;
#pragma unroll 1
    for (int j = 0; j < 8; j++) {
        int node = node0 + j;
        if (node >= n) return;
        float xr[F];
#pragma unroll
        for (int k = 0; k < F; k++) xr[k] = __ldg(&x[(long)node * F + k]);
        float* out = g_feat + out_off + (long)node * HID;
#pragma unroll
        for (int c0 = 0; c0 < HID; c0 += 32) {
            int c = c0 + lane;
            float acc = sb[c];
#pragma unroll
            for (int k = 0; k < F; k++) acc = fmaf(xr[k], sW[k * HID + c], acc);
            out[c] = acc;
        }
    }
}

template<int F>
__global__ void k_proj(const float* __restrict__ x, const float* __restrict__ W,
                       const float* __restrict__ b, int n, long out_off) {
    proj_body<F>(x, W, b, n, out_off);
}

// 4 agent-side projections in one launch (gridDim.y selects which)
__global__ void k_proj_ag(const float* __restrict__ x,
                          const float* W0, const float* b0,
                          const float* W1, const float* b1,
                          const float* W2, const float* b2,
                          const float* W3, const float* b3, int n) {
    const float* W; const float* b; long off;
    switch (blockIdx.y) {
        case 0: W = W0; b = b0; off = FD_S;  break;
        case 1: W = W1; b = b1; off = RES_S; break;
        case 2: W = W2; b = b2; off = FD_N;  break;
        default: W = W3; b = b3; off = RES_N; break;
    }
    proj_body<16>(x, W, b, n, off);
}

// ---------------- CSR build ----------------
__global__ void k_hist(const int* __restrict__ dst, int e, int cnt_off) {
    for (int i = blockIdx.x * blockDim.x + threadIdx.x; i < e;
         i += gridDim.x * blockDim.x)
        atomicAdd(&g_cnt[cnt_off + dst[i]], 1);
}

__global__ void k_scan(int n) {
    int g = blockIdx.x;                      // graph 0 (seen) / 1 (near)
    const int* cnt = g_cnt + g * NAG;
    int* off = g_off + g * (NAG + 1);
    int* cur = g_cur + g * NAG;
    __shared__ int s[512];
    int t = threadIdx.x;
    int per = (n + 511) / 512;
    int lo = t * per;
    int hi = lo + per; if (hi > n) hi = n;
    int sum = 0;
    for (int i = lo; i < hi; i++) sum += cnt[i];
    s[t] = sum;
    __syncthreads();
    for (int d = 1; d < 512; d <<= 1) {
        int v = (t >= d) ? s[t - d] : 0;
        __syncthreads();
        s[t] += v;
        __syncthreads();
    }
    int pre = (t == 0) ? 0 : s[t - 1];
    for (int i = lo; i < hi; i++) {
        off[i] = pre;
        cur[i] = pre;
        pre += cnt[i];
    }
    if (t == 0) off[n] = s[511];
}

__global__ void k_scatter(const int* __restrict__ dst, const int* __restrict__ src,
                          int e, int g, int perm_base) {
    for (int i = blockIdx.x * blockDim.x + threadIdx.x; i < e;
         i += gridDim.x * blockDim.x) {
        int p = atomicAdd(&g_cur[g * NAG + dst[i]], 1);
        g_perm[perm_base + p] = src[i];     // store src id directly
    }
}

// ---------------- GATv2: one (dst, head) per warp, single-pass online softmax ----
__global__ void k_gat(const float* __restrict__ attn,
                      long fs_off, long fd_off, long res_off,
                      int off_base, int perm_base, int xoff, int nag) {
    int warp = threadIdx.x >> 5, lane = threadIdx.x & 31;
    int dstn = blockIdx.x * 2 + (warp >> 2);
    if (dstn >= nag) return;
    int h = warp & 3;
    int base = h * Dh + lane * 2;
    float2 a   = *(const float2*)(attn + base);
    float2 fdv = *(const float2*)(g_feat + fd_off + (long)dstn * HID + base);
    float2 rv  = *(const float2*)(g_feat + res_off + (long)dstn * HID + base);
    int e0 = g_off[off_base + dstn], e1 = g_off[off_base + dstn + 1];

    float mx = -3.0e38f, den = 0.f, acc0 = 0.f, acc1 = 0.f;
    int s = (e0 < e1) ? g_perm[perm_base + e0] : 0;
    for (int i = e0; i < e1; i++) {
        float2 f = *(const float2*)(g_feat + fs_off + (long)s * HID + base);
        int sn = (i + 1 < e1) ? g_perm[perm_base + i + 1] : 0;   // prefetch
        float v0 = f.x + fdv.x; v0 = (v0 >= 0.f) ? v0 : 0.2f * v0;
        float v1 = f.y + fdv.y; v1 = (v1 >= 0.f) ? v1 : 0.2f * v1;
        float p = v0 * a.x + v1 * a.y;
#pragma unroll
        for (int o = 16; o; o >>= 1) p += __shfl_xor_sync(0xffffffffu, p, o);
        float nmx = fmaxf(mx, p);
        float scale = __expf(mx - nmx);      // 0 on first iter
        float ex = __expf(p - nmx);
        den  = den * scale + ex;
        acc0 = fmaf(acc0, scale, ex * f.x);
        acc1 = fmaf(acc1, scale, ex * f.y);
        mx = nmx;
        s = sn;
    }
    if (e1 == e0) den = 1.f;                 // zero-in-degree: rst = 0
    float o0 = fmaxf(acc0 / den + rv.x, 0.f);
    float o1 = fmaxf(acc1 / den + rv.y, 0.f);
    *(float2*)(g_xcat + (long)dstn * (2 * HID) + xoff + base) = make_float2(o0, o1);
}

// ---------------- final GEMM: out = relu(xcat[M,512] @ W[512,256] + b) ----------------
// 128x128 tile, 256 threads, 8x8 microtile
__global__ void k_gemm(const float* __restrict__ B, const float* __restrict__ bias,
                       float* __restrict__ C, int M) {
    const int K = 2 * HID, N = HID;
    __shared__ float sA[16][132];   // [k][m], padded (132*4B = 528B, 16B-aligned rows)
    __shared__ float sB[16][128];   // [k][n]
    int bm = blockIdx.y * 128, bn = blockIdx.x * 128;
    int tx = threadIdx.x & 15, ty = threadIdx.x >> 4;
    float acc[8][8] = {};
    for (int k0 = 0; k0 < K; k0 += 16) {
        // A tile: 128 rows x 16 cols = 512 float4
#pragma unroll
        for (int t = 0; t < 2; t++) {
            int idx = threadIdx.x + t * 256;
            int m = idx >> 2, k4 = (idx & 3) * 4;
            int gm = bm + m;
            float4 v = (gm < M) ? *(const float4*)(g_xcat + (long)gm * K + k0 + k4)
                                : make_float4(0.f, 0.f, 0.f, 0.f);
            sA[k4 + 0][m] = v.x; sA[k4 + 1][m] = v.y;
            sA[k4 + 2][m] = v.z; sA[k4 + 3][m] = v.w;
        }
        // B tile: 16 rows x 128 cols = 512 float4
#pragma unroll
        for (int t = 0; t < 2; t++) {
            int idx = threadIdx.x + t * 256;
            int k = idx >> 5, n4 = (idx & 31) * 4;
            *(float4*)(&sB[k][n4]) = *(const float4*)(B + (long)(k0 + k) * N + bn + n4);
        }
        __syncthreads();
#pragma unroll
        for (int k = 0; k < 16; k++) {
            float ar[8], br[8];
            *(float4*)(ar)     = *(const float4*)(&sA[k][ty * 4]);
            *(float4*)(ar + 4) = *(const float4*)(&sA[k][64 + ty * 4]);
            *(float4*)(br)     = *(const float4*)(&sB[k][tx * 4]);
            *(float4*)(br + 4) = *(const float4*)(&sB[k][64 + tx * 4]);
#pragma unroll
            for (int i = 0; i < 8; i++)
#pragma unroll
                for (int j = 0; j < 8; j++)
                    acc[i][j] = fmaf(ar[i], br[j], acc[i][j]);
        }
        __syncthreads();
    }
#pragma unroll
    for (int i = 0; i < 8; i++) {
        int m = bm + ((i < 4) ? (ty * 4 + i) : (64 + ty * 4 + i - 4));
        if (m >= M) continue;
#pragma unroll
        for (int j = 0; j < 8; j++) {
            int n = bn + ((j < 4) ? (tx * 4 + j) : (64 + tx * 4 + j - 4));
            C[(long)m * N + n] = fmaxf(acc[i][j] + bias[n], 0.f);
        }
    }
}

// ---------------- launch ----------------
extern "C" void kernel_launch(void* const* d_in, const int* in_sizes, int n_in,
                              void* d_out, int out_size) {
    const float* x_gt   = (const float*)d_in[0];
    const float* x_ubs  = (const float*)d_in[1];
    const float* x_ag   = (const float*)d_in[2];
    const int* seen_src = (const int*)d_in[3];
    const int* seen_dst = (const int*)d_in[4];
    const int* near_src = (const int*)d_in[5];
    const int* near_dst = (const int*)d_in[6];
    const float* Ws_seen = (const float*)d_in[7];
    const float* bs_seen = (const float*)d_in[8];
    const float* Wd_seen = (const float*)d_in[9];
    const float* bd_seen = (const float*)d_in[10];
    const float* attn_seen = (const float*)d_in[11];
    const float* Wr_seen = (const float*)d_in[12];
    const float* br_seen = (const float*)d_in[13];
    const float* Ws_near = (const float*)d_in[14];
    const float* bs_near = (const float*)d_in[15];
    const float* Wd_near = (const float*)d_in[16];
    const float* bd_near = (const float*)d_in[17];
    const float* attn_near = (const float*)d_in[18];
    const float* Wr_near = (const float*)d_in[19];
    const float* br_near = (const float*)d_in[20];
    const float* W_aggr  = (const float*)d_in[21];
    const float* b_aggr  = (const float*)d_in[22];
    float* out = (float*)d_out;

    int n_gt  = in_sizes[0] / 8;
    int n_ubs = in_sizes[1] / 8;
    int n_ag  = in_sizes[2] / 16;
    int e_seen = in_sizes[3];
    int e_near = in_sizes[5];

    k_zero<<<(2 * NAG + 255) / 256, 256>>>();

    k_proj<8><<<(n_gt + 63) / 64, 256>>>(x_gt, Ws_seen, bs_seen, n_gt, FS_SEEN);
    k_proj<8><<<(n_ubs + 63) / 64, 256>>>(x_ubs, Ws_near, bs_near, n_ubs, FS_NEAR);
    k_proj_ag<<<dim3((n_ag + 63) / 64, 4), 256>>>(x_ag,
        Wd_seen, bd_seen, Wr_seen, br_seen, Wd_near, bd_near, Wr_near, br_near, n_ag);

    k_hist<<<256, 256>>>(seen_dst, e_seen, 0);
    k_hist<<<256, 256>>>(near_dst, e_near, NAG);
    k_scan<<<2, 512>>>(n_ag);
    k_scatter<<<256, 256>>>(seen_dst, seen_src, e_seen, 0, 0);
    k_scatter<<<256, 256>>>(near_dst, near_src, e_near, 1, ESEEN);

    k_gat<<<(n_ag + 1) / 2, 256>>>(attn_seen, FS_SEEN, FD_S, RES_S,
                                   0, 0, 0, n_ag);
    k_gat<<<(n_ag + 1) / 2, 256>>>(attn_near, FS_NEAR, FD_N, RES_N,
                                   NAG + 1, ESEEN, HID, n_ag);

    k_gemm<<<dim3(HID / 128, (n_ag + 127) / 128), 256>>>(W_aggr, b_aggr, out, n_ag);
}

// round 3
// speedup vs baseline: 1.3743x; 1.1327x over previous
#include <cuda_runtime.h>

#define H 4
#define Dh 64
#define HID 256
#define NGT 100000
#define NUBS 20000
#define NAG 20000
#define ESEEN 320000
#define ENEAR 160000

// ---------------- scratch (device globals, no runtime alloc) ----------------
// g_feat layout: fs_seen | fs_near | fd_seen | res_seen | fd_near | res_near
__device__ float g_feat[(NGT + NUBS + 4 * NAG) * HID];
__device__ float g_xcat[NAG * 2 * HID];
__device__ int   g_cnt[2 * NAG];
__device__ int   g_cur[2 * NAG];
__device__ int   g_off[2 * (NAG + 1)];
__device__ int   g_perm[ESEEN + ENEAR];   // holds SRC node ids in dst-grouped order

#define FS_SEEN 0L
#define FS_NEAR ((long)NGT * HID)
#define FD_S    ((long)(NGT + NUBS) * HID)
#define RES_S   (FD_S + (long)NAG * HID)
#define FD_N    (RES_S + (long)NAG * HID)
#define RES_N   (FD_N + (long)NAG * HID)

// ---------------- zero counters ----------------
__global__ void k_zero() {
    int i = blockIdx.x * blockDim.x + threadIdx.x;
    if (i < 2 * NAG) g_cnt[i] = 0;
}

// ---------------- projection: out[n,256] = x[n,F] @ W[F,256] + b ----------------
// 64 nodes per block, 8 per warp. Lane owns 4 consecutive cols; W read as LDS.128.
template<int F>
__device__ __forceinline__ void proj_body(const float* __restrict__ x,
                                          const float* __restrict__ W,
                                          const float* __restrict__ b,
                                          int n, long out_off) {
    __shared__ float sW[16 * HID];
    __shared__ float sb[HID];
    for (int i = threadIdx.x; i < F * HID; i += blockDim.x) sW[i] = W[i];
    for (int i = threadIdx.x; i < HID; i += blockDim.x) sb[i] = b[i];
    __syncthreads();
    int warp = threadIdx.x >> 5, lane = threadIdx.x & 31;
    int node0 = blockIdx.x * 64 + warp * 8;
#pragma unroll 1
    for (int j = 0; j < 8; j++) {
        int node = node0 + j;
        if (node >= n) return;
        float xr[F];
#pragma unroll
        for (int k4 = 0; k4 < F; k4 += 4) {
            float4 xv = *(const float4*)(x + (long)node * F + k4);
            xr[k4] = xv.x; xr[k4 + 1] = xv.y; xr[k4 + 2] = xv.z; xr[k4 + 3] = xv.w;
        }
        float* out = g_feat + out_off + (long)node * HID;
#pragma unroll
        for (int cb = 0; cb < 2; cb++) {
            int c = cb * 128 + lane * 4;
            float4 acc = *(const float4*)(sb + c);
#pragma unroll
            for (int k = 0; k < F; k++) {
                float4 w = *(const float4*)(sW + k * HID + c);
                acc.x = fmaf(xr[k], w.x, acc.x);
                acc.y = fmaf(xr[k], w.y, acc.y);
                acc.z = fmaf(xr[k], w.z, acc.z);
                acc.w = fmaf(xr[k], w.w, acc.w);
            }
            *(float4*)(out + c) = acc;
        }
    }
}

template<int F>
__global__ void k_proj(const float* __restrict__ x, const float* __restrict__ W,
                       const float* __restrict__ b, int n, long out_off) {
    proj_body<F>(x, W, b, n, out_off);
}

// 4 agent-side projections in one launch (gridDim.y selects which)
__global__ void k_proj_ag(const float* __restrict__ x,
                          const float* W0, const float* b0,
                          const float* W1, const float* b1,
                          const float* W2, const float* b2,
                          const float* W3, const float* b3, int n) {
    const float* W; const float* b; long off;
    switch (blockIdx.y) {
        case 0: W = W0; b = b0; off = FD_S;  break;
        case 1: W = W1; b = b1; off = RES_S; break;
        case 2: W = W2; b = b2; off = FD_N;  break;
        default: W = W3; b = b3; off = RES_N; break;
    }
    proj_body<16>(x, W, b, n, off);
}

// ---------------- CSR build ----------------
__global__ void k_hist(const int* __restrict__ dst, int e, int cnt_off) {
    for (int i = blockIdx.x * blockDim.x + threadIdx.x; i < e;
         i += gridDim.x * blockDim.x)
        atomicAdd(&g_cnt[cnt_off + dst[i]], 1);
}

__global__ void k_scan(int n) {
    int g = blockIdx.x;                      // graph 0 (seen) / 1 (near)
    const int* cnt = g_cnt + g * NAG;
    int* off = g_off + g * (NAG + 1);
    int* cur = g_cur + g * NAG;
    __shared__ int s[512];
    int t = threadIdx.x;
    int per = (n + 511) / 512;
    int lo = t * per;
    int hi = lo + per; if (hi > n) hi = n;
    int sum = 0;
    for (int i = lo; i < hi; i++) sum += cnt[i];
    s[t] = sum;
    __syncthreads();
    for (int d = 1; d < 512; d <<= 1) {
        int v = (t >= d) ? s[t - d] : 0;
        __syncthreads();
        s[t] += v;
        __syncthreads();
    }
    int pre = (t == 0) ? 0 : s[t - 1];
    for (int i = lo; i < hi; i++) {
        off[i] = pre;
        cur[i] = pre;
        pre += cnt[i];
    }
    if (t == 0) off[n] = s[511];
}

__global__ void k_scatter(const int* __restrict__ dst, const int* __restrict__ src,
                          int e, int g, int perm_base) {
    for (int i = blockIdx.x * blockDim.x + threadIdx.x; i < e;
         i += gridDim.x * blockDim.x) {
        int p = atomicAdd(&g_cur[g * NAG + dst[i]], 1);
        g_perm[perm_base + p] = src[i];     // store src id directly
    }
}

// ---------------- GATv2: one (dst, head) per warp, chunk-of-4 online softmax ----
__device__ __forceinline__ float wreduce(float v) {
#pragma unroll
    for (int o = 16; o; o >>= 1) v += __shfl_xor_sync(0xffffffffu, v, o);
    return v;
}

__global__ void k_gat(const float* __restrict__ attnS,
                      const float* __restrict__ attnN, int nag) {
    int g = blockIdx.y;
    const float* attn = g ? attnN : attnS;
    long fs_off  = g ? FS_NEAR : FS_SEEN;
    long fd_off  = g ? FD_N    : FD_S;
    long res_off = g ? RES_N   : RES_S;
    int off_base = g ? (NAG + 1) : 0;
    int pb       = g ? ESEEN : 0;
    int xoff     = g ? HID : 0;

    int warp = threadIdx.x >> 5, lane = threadIdx.x & 31;
    int dstn = blockIdx.x * 2 + (warp >> 2);
    if (dstn >= nag) return;
    int h = warp & 3;
    int base = h * Dh + lane * 2;
    float2 a   = *(const float2*)(attn + base);
    float2 fdv = *(const float2*)(g_feat + fd_off + (long)dstn * HID + base);
    float2 rv  = *(const float2*)(g_feat + res_off + (long)dstn * HID + base);
    int e0 = g_off[off_base + dstn], e1 = g_off[off_base + dstn + 1];

    const float* fs = g_feat + fs_off;
    float mx = -3.0e38f, den = 0.f, acc0 = 0.f, acc1 = 0.f;

    for (int i = e0; i < e1; i += 4) {
        int r = e1 - i;
        // gather 4 src ids (uniform loads)
        int s0 = g_perm[pb + i];
        int s1 = (r > 1) ? g_perm[pb + i + 1] : s0;
        int s2 = (r > 2) ? g_perm[pb + i + 2] : s0;
        int s3 = (r > 3) ? g_perm[pb + i + 3] : s0;
        // 4 independent gathers (MLP=4)
        float2 f0 = *(const float2*)(fs + (long)s0 * HID + base);
        float2 f1 = *(const float2*)(fs + (long)s1 * HID + base);
        float2 f2 = *(const float2*)(fs + (long)s2 * HID + base);
        float2 f3 = *(const float2*)(fs + (long)s3 * HID + base);
        // per-edge leaky-relu dot partials
        float v0x = f0.x + fdv.x; v0x = (v0x >= 0.f) ? v0x : 0.2f * v0x;
        float v0y = f0.y + fdv.y; v0y = (v0y >= 0.f) ? v0y : 0.2f * v0y;
        float v1x = f1.x + fdv.x; v1x = (v1x >= 0.f) ? v1x : 0.2f * v1x;
        float v1y = f1.y + fdv.y; v1y = (v1y >= 0.f) ? v1y : 0.2f * v1y;
        float v2x = f2.x + fdv.x; v2x = (v2x >= 0.f) ? v2x : 0.2f * v2x;
        float v2y = f2.y + fdv.y; v2y = (v2y >= 0.f) ? v2y : 0.2f * v2y;
        float v3x = f3.x + fdv.x; v3x = (v3x >= 0.f) ? v3x : 0.2f * v3x;
        float v3y = f3.y + fdv.y; v3y = (v3y >= 0.f) ? v3y : 0.2f * v3y;
        float p0 = fmaf(v0x, a.x, v0y * a.y);
        float p1 = fmaf(v1x, a.x, v1y * a.y);
        float p2 = fmaf(v2x, a.x, v2y * a.y);
        float p3 = fmaf(v3x, a.x, v3y * a.y);
        // 4 pipelined (independent) warp reductions
#pragma unroll
        for (int o = 16; o; o >>= 1) {
            p0 += __shfl_xor_sync(0xffffffffu, p0, o);
            p1 += __shfl_xor_sync(0xffffffffu, p1, o);
            p2 += __shfl_xor_sync(0xffffffffu, p2, o);
            p3 += __shfl_xor_sync(0xffffffffu, p3, o);
        }
        // mask tail
        if (r < 2) p1 = -3.0e38f;
        if (r < 3) p2 = -3.0e38f;
        if (r < 4) p3 = -3.0e38f;
        // chunk-level online softmax: one rescale per chunk
        float cm = fmaxf(fmaxf(p0, p1), fmaxf(p2, p3));
        float nmx = fmaxf(mx, cm);
        float scale = __expf(mx - nmx);           // 0 on first chunk
        float x0 = __expf(p0 - nmx);
        float x1 = __expf(p1 - nmx);
        float x2 = __expf(p2 - nmx);
        float x3 = __expf(p3 - nmx);
        den = fmaf(den, scale, (x0 + x1) + (x2 + x3));
        float a0 = fmaf(x0, f0.x, x1 * f1.x);
        a0 = fmaf(x2, f2.x, a0); a0 = fmaf(x3, f3.x, a0);
        float a1 = fmaf(x0, f0.y, x1 * f1.y);
        a1 = fmaf(x2, f2.y, a1); a1 = fmaf(x3, f3.y, a1);
        acc0 = fmaf(acc0, scale, a0);
        acc1 = fmaf(acc1, scale, a1);
        mx = nmx;
    }
    if (e1 == e0) den = 1.f;                 // zero-in-degree: rst = 0
    float o0 = fmaxf(acc0 / den + rv.x, 0.f);
    float o1 = fmaxf(acc1 / den + rv.y, 0.f);
    *(float2*)(g_xcat + (long)dstn * (2 * HID) + xoff + base) = make_float2(o0, o1);
}

// ---------------- final GEMM: out = relu(xcat[M,512] @ W[512,256] + b) ----------------
// 128x128 tile, 256 threads, 8x8 microtile
__global__ void k_gemm(const float* __restrict__ B, const float* __restrict__ bias,
                       float* __restrict__ C, int M) {
    const int K = 2 * HID, N = HID;
    __shared__ float sA[16][132];
    __shared__ float sB[16][128];
    int bm = blockIdx.y * 128, bn = blockIdx.x * 128;
    int tx = threadIdx.x & 15, ty = threadIdx.x >> 4;
    float acc[8][8] = {};
    for (int k0 = 0; k0 < K; k0 += 16) {
#pragma unroll
        for (int t = 0; t < 2; t++) {
            int idx = threadIdx.x + t * 256;
            int m = idx >> 2, k4 = (idx & 3) * 4;
            int gm = bm + m;
            float4 v = (gm < M) ? *(const float4*)(g_xcat + (long)gm * K + k0 + k4)
                                : make_float4(0.f, 0.f, 0.f, 0.f);
            sA[k4 + 0][m] = v.x; sA[k4 + 1][m] = v.y;
            sA[k4 + 2][m] = v.z; sA[k4 + 3][m] = v.w;
        }
#pragma unroll
        for (int t = 0; t < 2; t++) {
            int idx = threadIdx.x + t * 256;
            int k = idx >> 5, n4 = (idx & 31) * 4;
            *(float4*)(&sB[k][n4]) = *(const float4*)(B + (long)(k0 + k) * N + bn + n4);
        }
        __syncthreads();
#pragma unroll
        for (int k = 0; k < 16; k++) {
            float ar[8], br[8];
            *(float4*)(ar)     = *(const float4*)(&sA[k][ty * 4]);
            *(float4*)(ar + 4) = *(const float4*)(&sA[k][64 + ty * 4]);
            *(float4*)(br)     = *(const float4*)(&sB[k][tx * 4]);
            *(float4*)(br + 4) = *(const float4*)(&sB[k][64 + tx * 4]);
#pragma unroll
            for (int i = 0; i < 8; i++)
#pragma unroll
                for (int j = 0; j < 8; j++)
                    acc[i][j] = fmaf(ar[i], br[j], acc[i][j]);
        }
        __syncthreads();
    }
#pragma unroll
    for (int i = 0; i < 8; i++) {
        int m = bm + ((i < 4) ? (ty * 4 + i) : (64 + ty * 4 + i - 4));
        if (m >= M) continue;
#pragma unroll
        for (int j = 0; j < 8; j++) {
            int n = bn + ((j < 4) ? (tx * 4 + j) : (64 + tx * 4 + j - 4));
            C[(long)m * N + n] = fmaxf(acc[i][j] + bias[n], 0.f);
        }
    }
}

// ---------------- launch ----------------
extern "C" void kernel_launch(void* const* d_in, const int* in_sizes, int n_in,
                              void* d_out, int out_size) {
    const float* x_gt   = (const float*)d_in[0];
    const float* x_ubs  = (const float*)d_in[1];
    const float* x_ag   = (const float*)d_in[2];
    const int* seen_src = (const int*)d_in[3];
    const int* seen_dst = (const int*)d_in[4];
    const int* near_src = (const int*)d_in[5];
    const int* near_dst = (const int*)d_in[6];
    const float* Ws_seen = (const float*)d_in[7];
    const float* bs_seen = (const float*)d_in[8];
    const float* Wd_seen = (const float*)d_in[9];
    const float* bd_seen = (const float*)d_in[10];
    const float* attn_seen = (const float*)d_in[11];
    const float* Wr_seen = (const float*)d_in[12];
    const float* br_seen = (const float*)d_in[13];
    const float* Ws_near = (const float*)d_in[14];
    const float* bs_near = (const float*)d_in[15];
    const float* Wd_near = (const float*)d_in[16];
    const float* bd_near = (const float*)d_in[17];
    const float* attn_near = (const float*)d_in[18];
    const float* Wr_near = (const float*)d_in[19];
    const float* br_near = (const float*)d_in[20];
    const float* W_aggr  = (const float*)d_in[21];
    const float* b_aggr  = (const float*)d_in[22];
    float* out = (float*)d_out;

    int n_gt  = in_sizes[0] / 8;
    int n_ubs = in_sizes[1] / 8;
    int n_ag  = in_sizes[2] / 16;
    int e_seen = in_sizes[3];
    int e_near = in_sizes[5];

    k_zero<<<(2 * NAG + 255) / 256, 256>>>();

    k_proj<8><<<(n_gt + 63) / 64, 256>>>(x_gt, Ws_seen, bs_seen, n_gt, FS_SEEN);
    k_proj<8><<<(n_ubs + 63) / 64, 256>>>(x_ubs, Ws_near, bs_near, n_ubs, FS_NEAR);
    k_proj_ag<<<dim3((n_ag + 63) / 64, 4), 256>>>(x_ag,
        Wd_seen, bd_seen, Wr_seen, br_seen, Wd_near, bd_near, Wr_near, br_near, n_ag);

    k_hist<<<256, 256>>>(seen_dst, e_seen, 0);
    k_hist<<<256, 256>>>(near_dst, e_near, NAG);
    k_scan<<<2, 512>>>(n_ag);
    k_scatter<<<256, 256>>>(seen_dst, seen_src, e_seen, 0, 0);
    k_scatter<<<256, 256>>>(near_dst, near_src, e_near, 1, ESEEN);

    k_gat<<<dim3((n_ag + 1) / 2, 2), 256>>>(attn_seen, attn_near, n_ag);

    k_gemm<<<dim3(HID / 128, (n_ag + 127) / 128), 256>>>(W_aggr, b_aggr, out, n_ag);
}

// round 4
// speedup vs baseline: 1.4804x; 1.0772x over previous
#include <cuda_runtime.h>

#define H 4
#define Dh 64
#define HID 256
#define NGT 100000
#define NUBS 20000
#define NAG 20000
#define ESEEN 320000
#define ENEAR 160000

typedef unsigned long long u64;

__device__ __forceinline__ u64 pk2(float lo, float hi) {
    u64 r; asm("mov.b64 %0,{%1,%2};" : "=l"(r) : "f"(lo), "f"(hi)); return r;
}
__device__ __forceinline__ u64 f2fma(u64 a, u64 b, u64 c) {
    u64 d; asm("fma.rn.f32x2 %0,%1,%2,%3;" : "=l"(d) : "l"(a), "l"(b), "l"(c)); return d;
}
__device__ __forceinline__ float2 upk2(u64 v) {
    float2 r; asm("mov.b64 {%0,%1},%2;" : "=f"(r.x), "=f"(r.y) : "l"(v)); return r;
}

// ---------------- scratch (device globals, no runtime alloc) ----------------
__device__ float g_feat[(NGT + NUBS + 4 * NAG) * HID];
__device__ float g_xcat[NAG * 2 * HID];
__device__ int   g_cnt[2 * NAG];
__device__ int   g_cur[2 * NAG];
__device__ int   g_off[2 * (NAG + 1)];
__device__ int   g_perm[ESEEN + ENEAR];   // SRC node ids in dst-grouped order

#define FS_SEEN 0L
#define FS_NEAR ((long)NGT * HID)
#define FD_S    ((long)(NGT + NUBS) * HID)
#define RES_S   (FD_S + (long)NAG * HID)
#define FD_N    (RES_S + (long)NAG * HID)
#define RES_N   (FD_N + (long)NAG * HID)

__global__ void k_zero() {
    int i = blockIdx.x * blockDim.x + threadIdx.x;
    if (i < 2 * NAG) g_cnt[i] = 0;
}

// ---------------- projection: out[n,256] = x[n,F] @ W[F,256] + b ----------------
// 64 nodes/block, 8 per warp. cb-outer: W column-slice cached in registers
// (as packed f32x2), nodes inner -> smem W read once per cb, FFMA2 inner product.
template<int F>
__device__ __forceinline__ void proj_body(const float* __restrict__ x,
                                          const float* __restrict__ W,
                                          const float* __restrict__ b,
                                          int n, long out_off) {
    __shared__ float sW[16 * HID];
    __shared__ float sb[HID];
    for (int i = threadIdx.x; i < F * HID; i += blockDim.x) sW[i] = W[i];
    for (int i = threadIdx.x; i < HID; i += blockDim.x) sb[i] = b[i];
    __syncthreads();
    int warp = threadIdx.x >> 5, lane = threadIdx.x & 31;
    int node0 = blockIdx.x * 64 + warp * 8;
    if (node0 >= n) return;
    int nlim = n - node0; if (nlim > 8) nlim = 8;
#pragma unroll
    for (int cb = 0; cb < 2; cb++) {
        int c = cb * 128 + lane * 4;
        u64 wp[F][2];
#pragma unroll
        for (int k = 0; k < F; k++) {
            ulonglong2 wv = *(const ulonglong2*)(sW + k * HID + c);
            wp[k][0] = wv.x; wp[k][1] = wv.y;
        }
        ulonglong2 bv = *(const ulonglong2*)(sb + c);
#pragma unroll 1
        for (int j = 0; j < nlim; j++) {
            int node = node0 + j;
            float xr[F];
#pragma unroll
            for (int k4 = 0; k4 < F; k4 += 4) {
                float4 xv = *(const float4*)(x + (long)node * F + k4);
                xr[k4] = xv.x; xr[k4 + 1] = xv.y; xr[k4 + 2] = xv.z; xr[k4 + 3] = xv.w;
            }
            u64 a0 = bv.x, a1 = bv.y;
#pragma unroll
            for (int k = 0; k < F; k++) {
                u64 xp = pk2(xr[k], xr[k]);
                a0 = f2fma(xp, wp[k][0], a0);
                a1 = f2fma(xp, wp[k][1], a1);
            }
            ulonglong2 ov; ov.x = a0; ov.y = a1;
            *(ulonglong2*)(g_feat + out_off + (long)node * HID + c) = ov;
        }
    }
}

template<int F>
__global__ void k_proj(const float* __restrict__ x, const float* __restrict__ W,
                       const float* __restrict__ b, int n, long out_off) {
    proj_body<F>(x, W, b, n, out_off);
}

__global__ void k_proj_ag(const float* __restrict__ x,
                          const float* W0, const float* b0,
                          const float* W1, const float* b1,
                          const float* W2, const float* b2,
                          const float* W3, const float* b3, int n) {
    const float* W; const float* b; long off;
    switch (blockIdx.y) {
        case 0: W = W0; b = b0; off = FD_S;  break;
        case 1: W = W1; b = b1; off = RES_S; break;
        case 2: W = W2; b = b2; off = FD_N;  break;
        default: W = W3; b = b3; off = RES_N; break;
    }
    proj_body<16>(x, W, b, n, off);
}

// ---------------- CSR build ----------------
__global__ void k_hist(const int* __restrict__ dst, int e, int cnt_off) {
    for (int i = blockIdx.x * blockDim.x + threadIdx.x; i < e;
         i += gridDim.x * blockDim.x)
        atomicAdd(&g_cnt[cnt_off + dst[i]], 1);
}

__global__ void k_scan(int n) {
    int g = blockIdx.x;
    const int* cnt = g_cnt + g * NAG;
    int* off = g_off + g * (NAG + 1);
    int* cur = g_cur + g * NAG;
    __shared__ int s[512];
    int t = threadIdx.x;
    int per = (n + 511) / 512;
    int lo = t * per;
    int hi = lo + per; if (hi > n) hi = n;
    int sum = 0;
    for (int i = lo; i < hi; i++) sum += cnt[i];
    s[t] = sum;
    __syncthreads();
    for (int d = 1; d < 512; d <<= 1) {
        int v = (t >= d) ? s[t - d] : 0;
        __syncthreads();
        s[t] += v;
        __syncthreads();
    }
    int pre = (t == 0) ? 0 : s[t - 1];
    for (int i = lo; i < hi; i++) {
        off[i] = pre;
        cur[i] = pre;
        pre += cnt[i];
    }
    if (t == 0) off[n] = s[511];
}

__global__ void k_scatter(const int* __restrict__ dst, const int* __restrict__ src,
                          int e, int g, int perm_base) {
    for (int i = blockIdx.x * blockDim.x + threadIdx.x; i < e;
         i += gridDim.x * blockDim.x) {
        int p = atomicAdd(&g_cur[g * NAG + dst[i]], 1);
        g_perm[perm_base + p] = src[i];
    }
}

// ---------------- GATv2: one (dst, head) per warp, pipelined chunk-of-4 ----
__global__ void k_gat(const float* __restrict__ attnS,
                      const float* __restrict__ attnN, int nag) {
    int g = blockIdx.y;
    const float* attn = g ? attnN : attnS;
    long fs_off  = g ? FS_NEAR : FS_SEEN;
    long fd_off  = g ? FD_N    : FD_S;
    long res_off = g ? RES_N   : RES_S;
    int off_base = g ? (NAG + 1) : 0;
    int pb       = g ? ESEEN : 0;
    int xoff     = g ? HID : 0;

    int warp = threadIdx.x >> 5, lane = threadIdx.x & 31;
    int dstn = blockIdx.x * 2 + (warp >> 2);
    if (dstn >= nag) return;
    int h = warp & 3;
    int base = h * Dh + lane * 2;
    float2 a   = *(const float2*)(attn + base);
    float2 fdv = *(const float2*)(g_feat + fd_off + (long)dstn * HID + base);
    float2 rv  = *(const float2*)(g_feat + res_off + (long)dstn * HID + base);
    int e0 = g_off[off_base + dstn], e1 = g_off[off_base + dstn + 1];

    const float* fs = g_feat + fs_off;
    const int* pp = g_perm + pb;

    auto load4 = [&](int j, float2& b0, float2& b1, float2& b2, float2& b3) {
        int rr = e1 - j;
        int s0 = pp[j];
        int s1 = (rr > 1) ? pp[j + 1] : s0;
        int s2 = (rr > 2) ? pp[j + 2] : s0;
        int s3 = (rr > 3) ? pp[j + 3] : s0;
        b0 = __ldg((const float2*)(fs + (long)s0 * HID + base));
        b1 = __ldg((const float2*)(fs + (long)s1 * HID + base));
        b2 = __ldg((const float2*)(fs + (long)s2 * HID + base));
        b3 = __ldg((const float2*)(fs + (long)s3 * HID + base));
    };

    float mx = -3.0e38f, den = 0.f, acc0 = 0.f, acc1 = 0.f;
    float2 f0 = make_float2(0.f, 0.f), f1 = f0, f2 = f0, f3 = f0;
    if (e0 < e1) load4(e0, f0, f1, f2, f3);

    for (int i = e0; i < e1; i += 4) {
        // prefetch next chunk (overlaps with compute below)
        float2 n0 = f0, n1 = f1, n2 = f2, n3 = f3;
        if (i + 4 < e1) load4(i + 4, n0, n1, n2, n3);

        int r = e1 - i;
        float v0x = f0.x + fdv.x; v0x = (v0x >= 0.f) ? v0x : 0.2f * v0x;
        float v0y = f0.y + fdv.y; v0y = (v0y >= 0.f) ? v0y : 0.2f * v0y;
        float v1x = f1.x + fdv.x; v1x = (v1x >= 0.f) ? v1x : 0.2f * v1x;
        float v1y = f1.y + fdv.y; v1y = (v1y >= 0.f) ? v1y : 0.2f * v1y;
        float v2x = f2.x + fdv.x; v2x = (v2x >= 0.f) ? v2x : 0.2f * v2x;
        float v2y = f2.y + fdv.y; v2y = (v2y >= 0.f) ? v2y : 0.2f * v2y;
        float v3x = f3.x + fdv.x; v3x = (v3x >= 0.f) ? v3x : 0.2f * v3x;
        float v3y = f3.y + fdv.y; v3y = (v3y >= 0.f) ? v3y : 0.2f * v3y;
        float p0 = fmaf(v0x, a.x, v0y * a.y);
        float p1 = fmaf(v1x, a.x, v1y * a.y);
        float p2 = fmaf(v2x, a.x, v2y * a.y);
        float p3 = fmaf(v3x, a.x, v3y * a.y);
#pragma unroll
        for (int o = 16; o; o >>= 1) {
            p0 += __shfl_xor_sync(0xffffffffu, p0, o);
            p1 += __shfl_xor_sync(0xffffffffu, p1, o);
            p2 += __shfl_xor_sync(0xffffffffu, p2, o);
            p3 += __shfl_xor_sync(0xffffffffu, p3, o);
        }
        if (r < 2) p1 = -3.0e38f;
        if (r < 3) p2 = -3.0e38f;
        if (r < 4) p3 = -3.0e38f;
        float cm = fmaxf(fmaxf(p0, p1), fmaxf(p2, p3));
        float nmx = fmaxf(mx, cm);
        float scale = __expf(mx - nmx);
        float x0 = __expf(p0 - nmx);
        float x1 = __expf(p1 - nmx);
        float x2 = __expf(p2 - nmx);
        float x3 = __expf(p3 - nmx);
        den = fmaf(den, scale, (x0 + x1) + (x2 + x3));
        float a0 = fmaf(x0, f0.x, x1 * f1.x);
        a0 = fmaf(x2, f2.x, a0); a0 = fmaf(x3, f3.x, a0);
        float a1 = fmaf(x0, f0.y, x1 * f1.y);
        a1 = fmaf(x2, f2.y, a1); a1 = fmaf(x3, f3.y, a1);
        acc0 = fmaf(acc0, scale, a0);
        acc1 = fmaf(acc1, scale, a1);
        mx = nmx;
        f0 = n0; f1 = n1; f2 = n2; f3 = n3;
    }
    if (e1 == e0) den = 1.f;
    float o0 = fmaxf(acc0 / den + rv.x, 0.f);
    float o1 = fmaxf(acc1 / den + rv.y, 0.f);
    *(float2*)(g_xcat + (long)dstn * (2 * HID) + xoff + base) = make_float2(o0, o1);
}

// ---------------- final GEMM: out = relu(xcat[M,512] @ W[512,256] + b) ----------------
// 128x128 tile, 256 threads, 8x8 microtile with packed f32x2 FMA
__global__ void __launch_bounds__(256) k_gemm(const float* __restrict__ B,
                                              const float* __restrict__ bias,
                                              float* __restrict__ C, int M) {
    const int K = 2 * HID, N = HID;
    __shared__ float sA[16][132];
    __shared__ float sB[16][128];
    int bm = blockIdx.y * 128, bn = blockIdx.x * 128;
    int tx = threadIdx.x & 15, ty = threadIdx.x >> 4;
    u64 acc[8][4] = {};   // [row i][col-pair jp]; jp 0,1 -> cols tx*4+{0..3}; jp 2,3 -> 64+tx*4+{0..3}
    for (int k0 = 0; k0 < K; k0 += 16) {
#pragma unroll
        for (int t = 0; t < 2; t++) {
            int idx = threadIdx.x + t * 256;
            int m = idx >> 2, k4 = (idx & 3) * 4;
            int gm = bm + m;
            float4 v = (gm < M) ? *(const float4*)(g_xcat + (long)gm * K + k0 + k4)
                                : make_float4(0.f, 0.f, 0.f, 0.f);
            sA[k4 + 0][m] = v.x; sA[k4 + 1][m] = v.y;
            sA[k4 + 2][m] = v.z; sA[k4 + 3][m] = v.w;
        }
#pragma unroll
        for (int t = 0; t < 2; t++) {
            int idx = threadIdx.x + t * 256;
            int k = idx >> 5, n4 = (idx & 31) * 4;
            *(float4*)(&sB[k][n4]) = *(const float4*)(B + (long)(k0 + k) * N + bn + n4);
        }
        __syncthreads();
#pragma unroll
        for (int k = 0; k < 16; k++) {
            float ar[8];
            *(float4*)(ar)     = *(const float4*)(&sA[k][ty * 4]);
            *(float4*)(ar + 4) = *(const float4*)(&sA[k][64 + ty * 4]);
            ulonglong2 b01 = *(const ulonglong2*)(&sB[k][tx * 4]);
            ulonglong2 b23 = *(const ulonglong2*)(&sB[k][64 + tx * 4]);
            u64 bp[4] = { b01.x, b01.y, b23.x, b23.y };
#pragma unroll
            for (int i = 0; i < 8; i++) {
                u64 ap = pk2(ar[i], ar[i]);
#pragma unroll
                for (int jp = 0; jp < 4; jp++)
                    acc[i][jp] = f2fma(ap, bp[jp], acc[i][jp]);
            }
        }
        __syncthreads();
    }
#pragma unroll
    for (int i = 0; i < 8; i++) {
        int m = bm + ((i < 4) ? (ty * 4 + i) : (64 + ty * 4 + i - 4));
        if (m >= M) continue;
#pragma unroll
        for (int jp = 0; jp < 4; jp++) {
            int n = bn + ((jp < 2) ? (tx * 4 + jp * 2) : (64 + tx * 4 + (jp - 2) * 2));
            float2 v = upk2(acc[i][jp]);
            v.x = fmaxf(v.x + bias[n], 0.f);
            v.y = fmaxf(v.y + bias[n + 1], 0.f);
            *(float2*)(C + (long)m * N + n) = v;
        }
    }
}

// ---------------- launch ----------------
extern "C" void kernel_launch(void* const* d_in, const int* in_sizes, int n_in,
                              void* d_out, int out_size) {
    const float* x_gt   = (const float*)d_in[0];
    const float* x_ubs  = (const float*)d_in[1];
    const float* x_ag   = (const float*)d_in[2];
    const int* seen_src = (const int*)d_in[3];
    const int* seen_dst = (const int*)d_in[4];
    const int* near_src = (const int*)d_in[5];
    const int* near_dst = (const int*)d_in[6];
    const float* Ws_seen = (const float*)d_in[7];
    const float* bs_seen = (const float*)d_in[8];
    const float* Wd_seen = (const float*)d_in[9];
    const float* bd_seen = (const float*)d_in[10];
    const float* attn_seen = (const float*)d_in[11];
    const float* Wr_seen = (const float*)d_in[12];
    const float* br_seen = (const float*)d_in[13];
    const float* Ws_near = (const float*)d_in[14];
    const float* bs_near = (const float*)d_in[15];
    const float* Wd_near = (const float*)d_in[16];
    const float* bd_near = (const float*)d_in[17];
    const float* attn_near = (const float*)d_in[18];
    const float* Wr_near = (const float*)d_in[19];
    const float* br_near = (const float*)d_in[20];
    const float* W_aggr  = (const float*)d_in[21];
    const float* b_aggr  = (const float*)d_in[22];
    float* out = (float*)d_out;

    int n_gt  = in_sizes[0] / 8;
    int n_ubs = in_sizes[1] / 8;
    int n_ag  = in_sizes[2] / 16;
    int e_seen = in_sizes[3];
    int e_near = in_sizes[5];

    k_zero<<<(2 * NAG + 255) / 256, 256>>>();

    k_proj<8><<<(n_gt + 63) / 64, 256>>>(x_gt, Ws_seen, bs_seen, n_gt, FS_SEEN);
    k_proj<8><<<(n_ubs + 63) / 64, 256>>>(x_ubs, Ws_near, bs_near, n_ubs, FS_NEAR);
    k_proj_ag<<<dim3((n_ag + 63) / 64, 4), 256>>>(x_ag,
        Wd_seen, bd_seen, Wr_seen, br_seen, Wd_near, bd_near, Wr_near, br_near, n_ag);

    k_hist<<<256, 256>>>(seen_dst, e_seen, 0);
    k_hist<<<256, 256>>>(near_dst, e_near, NAG);
    k_scan<<<2, 512>>>(n_ag);
    k_scatter<<<256, 256>>>(seen_dst, seen_src, e_seen, 0, 0);
    k_scatter<<<256, 256>>>(near_dst, near_src, e_near, 1, ESEEN);

    k_gat<<<dim3((n_ag + 1) / 2, 2), 256>>>(attn_seen, attn_near, n_ag);

    k_gemm<<<dim3(HID / 128, (n_ag + 127) / 128), 256>>>(W_aggr, b_aggr, out, n_ag);
}

// round 5
// speedup vs baseline: 1.8265x; 1.2338x over previous
#include <cuda_runtime.h>

#define H 4
#define Dh 64
#define HID 256
#define NGT 100000
#define NUBS 20000
#define NAG 20000
#define ESEEN 320000
#define ENEAR 160000

typedef unsigned long long u64;

__device__ __forceinline__ u64 pk2(float lo, float hi) {
    u64 r; asm("mov.b64 %0,{%1,%2};" : "=l"(r) : "f"(lo), "f"(hi)); return r;
}
__device__ __forceinline__ u64 f2fma(u64 a, u64 b, u64 c) {
    u64 d; asm("fma.rn.f32x2 %0,%1,%2,%3;" : "=l"(d) : "l"(a), "l"(b), "l"(c)); return d;
}
__device__ __forceinline__ float2 upk2(u64 v) {
    float2 r; asm("mov.b64 {%0,%1},%2;" : "=f"(r.x), "=f"(r.y) : "l"(v)); return r;
}

// ---------------- scratch (device globals, no runtime alloc) ----------------
__device__ float g_feat[(NGT + NUBS + 4 * NAG) * HID];
__device__ float g_xcat[NAG * 2 * HID];
__device__ int   g_cnt[2 * NAG];
__device__ int   g_cur[2 * NAG];
__device__ int   g_off[2 * (NAG + 1)];
__device__ int   g_perm[ESEEN + ENEAR];   // SRC node ids in dst-grouped order

#define FS_SEEN 0L
#define FS_NEAR ((long)NGT * HID)
#define FD_S    ((long)(NGT + NUBS) * HID)
#define RES_S   (FD_S + (long)NAG * HID)
#define FD_N    (RES_S + (long)NAG * HID)
#define RES_N   (FD_N + (long)NAG * HID)

__global__ void k_zero() {
    int i = blockIdx.x * blockDim.x + threadIdx.x;
    if (i < 2 * NAG) g_cnt[i] = 0;
}

// ---------------- fused projections ----------------
// Block: 128 nodes x 256 cols. 8 warps: warp w -> col slice (w&3)*64,
// node half (w>>2)*64. Lane owns 2 cols; W cached as 16 u64 regs.
template<int F>
__device__ __forceinline__ void proj_body(const float* __restrict__ x,
                                          const float* __restrict__ W,
                                          const float* __restrict__ b,
                                          int n, long out_off) {
    int node0 = blockIdx.x * 128;
    if (node0 >= n) return;
    __shared__ float sx[128 * 16];
    int cnt = n - node0; if (cnt > 128) cnt = 128;
    int nf4 = (cnt * F) >> 2;
    for (int i = threadIdx.x; i < nf4; i += 256)
        *(float4*)(sx + i * 4) = *(const float4*)(x + (long)node0 * F + i * 4);
    __syncthreads();

    int warp = threadIdx.x >> 5, lane = threadIdx.x & 31;
    int c = (warp & 3) * 64 + (lane << 1);
    int nh = (warp >> 2) * 64;
    u64 wp[F];
#pragma unroll
    for (int k = 0; k < F; k++) wp[k] = *(const u64*)(W + k * HID + c);
    u64 bp = *(const u64*)(b + c);

    int jend = nh + 64; if (jend > cnt) jend = cnt;
#pragma unroll 1
    for (int j = nh; j < jend; j++) {
        const float* xr = sx + j * F;
        u64 acc = bp;
#pragma unroll
        for (int k4 = 0; k4 < F; k4 += 4) {
            float4 xv = *(const float4*)(xr + k4);
            acc = f2fma(pk2(xv.x, xv.x), wp[k4 + 0], acc);
            acc = f2fma(pk2(xv.y, xv.y), wp[k4 + 1], acc);
            acc = f2fma(pk2(xv.z, xv.z), wp[k4 + 2], acc);
            acc = f2fma(pk2(xv.w, xv.w), wp[k4 + 3], acc);
        }
        *(u64*)(g_feat + out_off + (long)(node0 + j) * HID + c) = acc;
    }
}

__global__ void k_proj_all(const float* xg, const float* xu, const float* xa,
                           const float* Wsg, const float* bsg,
                           const float* Wsu, const float* bsu,
                           const float* W0, const float* b0,
                           const float* W1, const float* b1,
                           const float* W2, const float* b2,
                           const float* W3, const float* b3,
                           int n_gt, int n_ubs, int n_ag) {
    switch (blockIdx.y) {
        case 0: proj_body<8>(xg, Wsg, bsg, n_gt, FS_SEEN); break;
        case 1: proj_body<8>(xu, Wsu, bsu, n_ubs, FS_NEAR); break;
        case 2: proj_body<16>(xa, W0, b0, n_ag, FD_S);  break;
        case 3: proj_body<16>(xa, W1, b1, n_ag, RES_S); break;
        case 4: proj_body<16>(xa, W2, b2, n_ag, FD_N);  break;
        default: proj_body<16>(xa, W3, b3, n_ag, RES_N); break;
    }
}

// ---------------- CSR build (both graphs per launch via gridDim.y) ----------------
__global__ void k_hist(const int* __restrict__ dA, int eA,
                       const int* __restrict__ dB, int eB) {
    int g = blockIdx.y;
    const int* dst = g ? dB : dA;
    int e = g ? eB : eA;
    int co = g ? NAG : 0;
    for (int i = blockIdx.x * blockDim.x + threadIdx.x; i < e;
         i += gridDim.x * blockDim.x)
        atomicAdd(&g_cnt[co + dst[i]], 1);
}

__global__ void k_scan(int n) {
    int g = blockIdx.x;
    const int* cnt = g_cnt + g * NAG;
    int* off = g_off + g * (NAG + 1);
    int* cur = g_cur + g * NAG;
    __shared__ int s[512];
    int t = threadIdx.x;
    int per = (n + 511) / 512;
    int lo = t * per;
    int hi = lo + per; if (hi > n) hi = n;
    int sum = 0;
    for (int i = lo; i < hi; i++) sum += cnt[i];
    s[t] = sum;
    __syncthreads();
    for (int d = 1; d < 512; d <<= 1) {
        int v = (t >= d) ? s[t - d] : 0;
        __syncthreads();
        s[t] += v;
        __syncthreads();
    }
    int pre = (t == 0) ? 0 : s[t - 1];
    for (int i = lo; i < hi; i++) {
        off[i] = pre;
        cur[i] = pre;
        pre += cnt[i];
    }
    if (t == 0) off[n] = s[511];
}

__global__ void k_scatter(const int* __restrict__ dA, const int* __restrict__ sA, int eA,
                          const int* __restrict__ dB, const int* __restrict__ sB, int eB) {
    int g = blockIdx.y;
    const int* dst = g ? dB : dA;
    const int* src = g ? sB : sA;
    int e = g ? eB : eA;
    int pb = g ? ESEEN : 0;
    for (int i = blockIdx.x * blockDim.x + threadIdx.x; i < e;
         i += gridDim.x * blockDim.x) {
        int p = atomicAdd(&g_cur[g * NAG + dst[i]], 1);
        g_perm[pb + p] = src[i];
    }
}

// ---------------- GATv2: one warp per dst, all 4 heads; chunk-of-4 ----------------
__device__ __forceinline__ float lrelu(float v) { return (v >= 0.f) ? v : 0.2f * v; }

__device__ __forceinline__ float escore(float4 fa, float4 fb, float4 d0, float4 d1,
                                        float4 a0, float4 a1) {
    float p;
    p = lrelu(fa.x + d0.x) * a0.x;
    p = fmaf(lrelu(fa.y + d0.y), a0.y, p);
    p = fmaf(lrelu(fa.z + d0.z), a0.z, p);
    p = fmaf(lrelu(fa.w + d0.w), a0.w, p);
    p = fmaf(lrelu(fb.x + d1.x), a1.x, p);
    p = fmaf(lrelu(fb.y + d1.y), a1.y, p);
    p = fmaf(lrelu(fb.z + d1.z), a1.z, p);
    p = fmaf(lrelu(fb.w + d1.w), a1.w, p);
    return p;
}

__global__ void __launch_bounds__(256) k_gat(const float* __restrict__ attnS,
                                             const float* __restrict__ attnN, int nag) {
    int g = blockIdx.y;
    const float* attn = g ? attnN : attnS;
    long fs_off  = g ? FS_NEAR : FS_SEEN;
    long fd_off  = g ? FD_N    : FD_S;
    long res_off = g ? RES_N   : RES_S;
    int off_base = g ? (NAG + 1) : 0;
    int pb       = g ? ESEEN : 0;
    int xoff     = g ? HID : 0;

    int warp = threadIdx.x >> 5, lane = threadIdx.x & 31;
    int dstn = blockIdx.x * 8 + warp;
    if (dstn >= nag) return;
    int off = lane * 8;                          // lane's 8 floats within row

    float4 a0 = __ldg((const float4*)(attn + off));
    float4 a1 = __ldg((const float4*)(attn + off + 4));
    const float* fdr = g_feat + fd_off + (long)dstn * HID + off;
    float4 d0 = *(const float4*)(fdr);
    float4 d1 = *(const float4*)(fdr + 4);
    const float* rvr = g_feat + res_off + (long)dstn * HID + off;
    float4 r0 = *(const float4*)(rvr);
    float4 r1 = *(const float4*)(rvr + 4);

    int e0 = g_off[off_base + dstn], e1 = g_off[off_base + dstn + 1];
    const float* fs = g_feat + fs_off;
    const int* pp = g_perm + pb;

    int id0 = 0, id1 = 0, id2 = 0, id3 = 0;
    if (e0 < e1) {
        int rr = e1 - e0;
        id0 = pp[e0];
        id1 = (rr > 1) ? pp[e0 + 1] : id0;
        id2 = (rr > 2) ? pp[e0 + 2] : id0;
        id3 = (rr > 3) ? pp[e0 + 3] : id0;
    }

    float mx = -3.0e38f, den = 0.f;
    float4 acc0 = make_float4(0.f, 0.f, 0.f, 0.f), acc1 = acc0;

    for (int i = e0; i < e1; i += 4) {
        const float* p0r = fs + (long)id0 * HID + off;
        const float* p1r = fs + (long)id1 * HID + off;
        const float* p2r = fs + (long)id2 * HID + off;
        const float* p3r = fs + (long)id3 * HID + off;
        float4 f0a = __ldg((const float4*)p0r), f0b = __ldg((const float4*)(p0r + 4));
        float4 f1a = __ldg((const float4*)p1r), f1b = __ldg((const float4*)(p1r + 4));
        float4 f2a = __ldg((const float4*)p2r), f2b = __ldg((const float4*)(p2r + 4));
        float4 f3a = __ldg((const float4*)p3r), f3b = __ldg((const float4*)(p3r + 4));

        // prefetch next chunk's ids while gathers are in flight
        if (i + 4 < e1) {
            int j = i + 4, rr = e1 - j;
            id0 = pp[j];
            id1 = (rr > 1) ? pp[j + 1] : id0;
            id2 = (rr > 2) ? pp[j + 2] : id0;
            id3 = (rr > 3) ? pp[j + 3] : id0;
        }

        float p0 = escore(f0a, f0b, d0, d1, a0, a1);
        float p1 = escore(f1a, f1b, d0, d1, a0, a1);
        float p2 = escore(f2a, f2b, d0, d1, a0, a1);
        float p3 = escore(f3a, f3b, d0, d1, a0, a1);
        // segmented sum over the 8 lanes of this head
#pragma unroll
        for (int o = 1; o < 8; o <<= 1) {
            p0 += __shfl_xor_sync(0xffffffffu, p0, o);
            p1 += __shfl_xor_sync(0xffffffffu, p1, o);
            p2 += __shfl_xor_sync(0xffffffffu, p2, o);
            p3 += __shfl_xor_sync(0xffffffffu, p3, o);
        }
        int r = e1 - i;
        if (r < 2) p1 = -3.0e38f;
        if (r < 3) p2 = -3.0e38f;
        if (r < 4) p3 = -3.0e38f;

        float cm = fmaxf(fmaxf(p0, p1), fmaxf(p2, p3));
        float nmx = fmaxf(mx, cm);
        float scale = __expf(mx - nmx);
        float x0 = __expf(p0 - nmx);
        float x1 = __expf(p1 - nmx);
        float x2 = __expf(p2 - nmx);
        float x3 = __expf(p3 - nmx);
        den = fmaf(den, scale, (x0 + x1) + (x2 + x3));
        acc0.x = fmaf(acc0.x, scale, fmaf(x0, f0a.x, fmaf(x1, f1a.x, fmaf(x2, f2a.x, x3 * f3a.x))));
        acc0.y = fmaf(acc0.y, scale, fmaf(x0, f0a.y, fmaf(x1, f1a.y, fmaf(x2, f2a.y, x3 * f3a.y))));
        acc0.z = fmaf(acc0.z, scale, fmaf(x0, f0a.z, fmaf(x1, f1a.z, fmaf(x2, f2a.z, x3 * f3a.z))));
        acc0.w = fmaf(acc0.w, scale, fmaf(x0, f0a.w, fmaf(x1, f1a.w, fmaf(x2, f2a.w, x3 * f3a.w))));
        acc1.x = fmaf(acc1.x, scale, fmaf(x0, f0b.x, fmaf(x1, f1b.x, fmaf(x2, f2b.x, x3 * f3b.x))));
        acc1.y = fmaf(acc1.y, scale, fmaf(x0, f0b.y, fmaf(x1, f1b.y, fmaf(x2, f2b.y, x3 * f3b.y))));
        acc1.z = fmaf(acc1.z, scale, fmaf(x0, f0b.z, fmaf(x1, f1b.z, fmaf(x2, f2b.z, x3 * f3b.z))));
        acc1.w = fmaf(acc1.w, scale, fmaf(x0, f0b.w, fmaf(x1, f1b.w, fmaf(x2, f2b.w, x3 * f3b.w))));
        mx = nmx;
    }
    float inv = (e1 == e0) ? 1.f : (1.f / den);
    float4 o0, o1;
    o0.x = fmaxf(fmaf(acc0.x, inv, r0.x), 0.f);
    o0.y = fmaxf(fmaf(acc0.y, inv, r0.y), 0.f);
    o0.z = fmaxf(fmaf(acc0.z, inv, r0.z), 0.f);
    o0.w = fmaxf(fmaf(acc0.w, inv, r0.w), 0.f);
    o1.x = fmaxf(fmaf(acc1.x, inv, r1.x), 0.f);
    o1.y = fmaxf(fmaf(acc1.y, inv, r1.y), 0.f);
    o1.z = fmaxf(fmaf(acc1.z, inv, r1.z), 0.f);
    o1.w = fmaxf(fmaf(acc1.w, inv, r1.w), 0.f);
    float* ox = g_xcat + (long)dstn * (2 * HID) + xoff + off;
    *(float4*)(ox) = o0;
    *(float4*)(ox + 4) = o1;
}

// ---------------- final GEMM: out = relu(xcat[M,512] @ W[512,256] + b) ----------------
__global__ void __launch_bounds__(256) k_gemm(const float* __restrict__ B,
                                              const float* __restrict__ bias,
                                              float* __restrict__ C, int M) {
    const int K = 2 * HID, N = HID;
    __shared__ float sA[16][132];
    __shared__ float sB[16][128];
    int bm = blockIdx.y * 128, bn = blockIdx.x * 128;
    int tx = threadIdx.x & 15, ty = threadIdx.x >> 4;
    u64 acc[8][4] = {};
    for (int k0 = 0; k0 < K; k0 += 16) {
#pragma unroll
        for (int t = 0; t < 2; t++) {
            int idx = threadIdx.x + t * 256;
            int m = idx >> 2, k4 = (idx & 3) * 4;
            int gm = bm + m;
            float4 v = (gm < M) ? *(const float4*)(g_xcat + (long)gm * K + k0 + k4)
                                : make_float4(0.f, 0.f, 0.f, 0.f);
            sA[k4 + 0][m] = v.x; sA[k4 + 1][m] = v.y;
            sA[k4 + 2][m] = v.z; sA[k4 + 3][m] = v.w;
        }
#pragma unroll
        for (int t = 0; t < 2; t++) {
            int idx = threadIdx.x + t * 256;
            int k = idx >> 5, n4 = (idx & 31) * 4;
            *(float4*)(&sB[k][n4]) = *(const float4*)(B + (long)(k0 + k) * N + bn + n4);
        }
        __syncthreads();
#pragma unroll
        for (int k = 0; k < 16; k++) {
            float ar[8];
            *(float4*)(ar)     = *(const float4*)(&sA[k][ty * 4]);
            *(float4*)(ar + 4) = *(const float4*)(&sA[k][64 + ty * 4]);
            ulonglong2 b01 = *(const ulonglong2*)(&sB[k][tx * 4]);
            ulonglong2 b23 = *(const ulonglong2*)(&sB[k][64 + tx * 4]);
            u64 bp[4] = { b01.x, b01.y, b23.x, b23.y };
#pragma unroll
            for (int i = 0; i < 8; i++) {
                u64 ap = pk2(ar[i], ar[i]);
#pragma unroll
                for (int jp = 0; jp < 4; jp++)
                    acc[i][jp] = f2fma(ap, bp[jp], acc[i][jp]);
            }
        }
        __syncthreads();
    }
#pragma unroll
    for (int i = 0; i < 8; i++) {
        int m = bm + ((i < 4) ? (ty * 4 + i) : (64 + ty * 4 + i - 4));
        if (m >= M) continue;
#pragma unroll
        for (int jp = 0; jp < 4; jp++) {
            int n = bn + ((jp < 2) ? (tx * 4 + jp * 2) : (64 + tx * 4 + (jp - 2) * 2));
            float2 v = upk2(acc[i][jp]);
            v.x = fmaxf(v.x + bias[n], 0.f);
            v.y = fmaxf(v.y + bias[n + 1], 0.f);
            *(float2*)(C + (long)m * N + n) = v;
        }
    }
}

// ---------------- launch ----------------
extern "C" void kernel_launch(void* const* d_in, const int* in_sizes, int n_in,
                              void* d_out, int out_size) {
    const float* x_gt   = (const float*)d_in[0];
    const float* x_ubs  = (const float*)d_in[1];
    const float* x_ag   = (const float*)d_in[2];
    const int* seen_src = (const int*)d_in[3];
    const int* seen_dst = (const int*)d_in[4];
    const int* near_src = (const int*)d_in[5];
    const int* near_dst = (const int*)d_in[6];
    const float* Ws_seen = (const float*)d_in[7];
    const float* bs_seen = (const float*)d_in[8];
    const float* Wd_seen = (const float*)d_in[9];
    const float* bd_seen = (const float*)d_in[10];
    const float* attn_seen = (const float*)d_in[11];
    const float* Wr_seen = (const float*)d_in[12];
    const float* br_seen = (const float*)d_in[13];
    const float* Ws_near = (const float*)d_in[14];
    const float* bs_near = (const float*)d_in[15];
    const float* Wd_near = (const float*)d_in[16];
    const float* bd_near = (const float*)d_in[17];
    const float* attn_near = (const float*)d_in[18];
    const float* Wr_near = (const float*)d_in[19];
    const float* br_near = (const float*)d_in[20];
    const float* W_aggr  = (const float*)d_in[21];
    const float* b_aggr  = (const float*)d_in[22];
    float* out = (float*)d_out;

    int n_gt  = in_sizes[0] / 8;
    int n_ubs = in_sizes[1] / 8;
    int n_ag  = in_sizes[2] / 16;
    int e_seen = in_sizes[3];
    int e_near = in_sizes[5];

    k_zero<<<(2 * NAG + 255) / 256, 256>>>();

    int pbx = (n_gt + 127) / 128;
    k_proj_all<<<dim3(pbx, 6), 256>>>(x_gt, x_ubs, x_ag,
        Ws_seen, bs_seen, Ws_near, bs_near,
        Wd_seen, bd_seen, Wr_seen, br_seen,
        Wd_near, bd_near, Wr_near, br_near,
        n_gt, n_ubs, n_ag);

    k_hist<<<dim3(256, 2), 256>>>(seen_dst, e_seen, near_dst, e_near);
    k_scan<<<2, 512>>>(n_ag);
    k_scatter<<<dim3(256, 2), 256>>>(seen_dst, seen_src, e_seen,
                                     near_dst, near_src, e_near);

    k_gat<<<dim3((n_ag + 7) / 8, 2), 256>>>(attn_seen, attn_near, n_ag);

    k_gemm<<<dim3(HID / 128, (n_ag + 127) / 128), 256>>>(W_aggr, b_aggr, out, n_ag);
}